// round 1
// baseline (speedup 1.0000x reference)
#include <cuda_runtime.h>

#define K          84
#define PAIRS      42          // K/2  (f32x2 pairs)
#define CHUNKS     21          // K/4  (float4 chunks)
#define NPROTO     10
#define THREADS    128
#define ROWS_TILE  256         // 2 rows per thread

// dynamic smem layout (floats):
//   s_x  [ROWS_TILE*K]  = 21504 floats (86016 B)
//   s_w  [NPROTO*K]     =   840 floats
//   s_w2 [NPROTO + pad] =    16 floats
#define SMEM_FLOATS (ROWS_TILE*K + NPROTO*K + 16)

__device__ __forceinline__ void ffma2(unsigned long long &d,
                                      unsigned long long a,
                                      unsigned long long b) {
    // packed f32x2 fma: d = a*b + d  (Blackwell sm_100+)
    asm("fma.rn.f32x2 %0, %1, %2, %0;" : "+l"(d) : "l"(a), "l"(b));
}
__device__ __forceinline__ float f2lo(unsigned long long v) {
    return __int_as_float((unsigned)(v & 0xffffffffULL));
}
__device__ __forceinline__ float f2hi(unsigned long long v) {
    return __int_as_float((unsigned)(v >> 32));
}

__global__ void __launch_bounds__(THREADS, 2)
rbf_kernel(const float* __restrict__ x,
           const float* __restrict__ weight,
           float* __restrict__ out,
           int nrows) {
    extern __shared__ __align__(16) float smem[];
    float* s_x  = smem;                     // [ROWS_TILE*K]
    float* s_w  = smem + ROWS_TILE * K;     // [NPROTO*K]
    float* s_w2 = s_w + NPROTO * K;         // [NPROTO]

    const int t = threadIdx.x;
    const long long row0 = (long long)blockIdx.x * ROWS_TILE;

    // ---- stage x tile (coalesced float4) ----
    {
        const float4* gx = (const float4*)(x + row0 * K);
        float4* sx = (float4*)s_x;
        const long long total4 = ((long long)nrows * K) / 4;
        const long long base4  = row0 * K / 4;
        #pragma unroll
        for (int i = 0; i < (ROWS_TILE * K / 4) / THREADS; i++) {
            long long g = base4 + i * THREADS + t;
            if (g < total4) sx[i * THREADS + t] = gx[i * THREADS + t];
        }
    }
    // ---- stage weights (840 floats) ----
    {
        const float4* gw = (const float4*)weight;
        float4* sw = (float4*)s_w;
        #pragma unroll
        for (int i = t; i < (NPROTO * K) / 4; i += THREADS) sw[i] = gw[i];
    }
    __syncthreads();

    // ---- w2 (threads 0..9) ----
    if (t < NPROTO) {
        float s = 0.f;
        #pragma unroll
        for (int j = 0; j < K; j++) { float w = s_w[t * K + j]; s += w * w; }
        s_w2[t] = s;
    }
    __syncthreads();

    // ---- compute: 2 rows per thread, f32x2 packed FMAs ----
    const long long rA = row0 + t;
    const long long rB = row0 + t + THREADS;
    const bool okA = rA < nrows;
    const bool okB = rB < nrows;

    const ulonglong2* rowA = (const ulonglong2*)(s_x + t * K);
    const ulonglong2* rowB = (const ulonglong2*)(s_x + (t + THREADS) * K);
    const unsigned long long* sw2p = (const unsigned long long*)s_w;

    unsigned long long accA[NPROTO], accB[NPROTO];
    unsigned long long x2a = 0ULL, x2b = 0ULL;
    #pragma unroll
    for (int k = 0; k < NPROTO; k++) { accA[k] = 0ULL; accB[k] = 0ULL; }

    #pragma unroll
    for (int c = 0; c < CHUNKS; c++) {
        ulonglong2 va = rowA[c];
        ulonglong2 vb = rowB[c];
        ffma2(x2a, va.x, va.x);
        ffma2(x2a, va.y, va.y);
        ffma2(x2b, vb.x, vb.x);
        ffma2(x2b, vb.y, vb.y);
        #pragma unroll
        for (int k = 0; k < NPROTO; k++) {
            unsigned long long w0 = sw2p[k * PAIRS + 2 * c];
            unsigned long long w1 = sw2p[k * PAIRS + 2 * c + 1];
            ffma2(accA[k], va.x, w0);
            ffma2(accA[k], va.y, w1);
            ffma2(accB[k], vb.x, w0);
            ffma2(accB[k], vb.y, w1);
        }
    }

    float x2A = f2lo(x2a) + f2hi(x2a);
    float x2B = f2lo(x2b) + f2hi(x2b);

    float resA[NPROTO], resB[NPROTO];
    #pragma unroll
    for (int k = 0; k < NPROTO; k++) {
        float w2 = s_w2[k];
        resA[k] = fmaf(-2.f, f2lo(accA[k]) + f2hi(accA[k]), x2A + w2);
        resB[k] = fmaf(-2.f, f2lo(accB[k]) + f2hi(accB[k]), x2B + w2);
    }

    if (okA) {
        float2* o = (float2*)(out + rA * NPROTO);
        #pragma unroll
        for (int k = 0; k < 5; k++) o[k] = make_float2(resA[2 * k], resA[2 * k + 1]);
    }
    if (okB) {
        float2* o = (float2*)(out + rB * NPROTO);
        #pragma unroll
        for (int k = 0; k < 5; k++) o[k] = make_float2(resB[2 * k], resB[2 * k + 1]);
    }
}

extern "C" void kernel_launch(void* const* d_in, const int* in_sizes, int n_in,
                              void* d_out, int out_size) {
    const float* x = (const float*)d_in[0];
    const float* w = (const float*)d_in[1];
    float* out = (float*)d_out;

    const int nrows = in_sizes[0] / K;   // 524288
    const int smem_bytes = SMEM_FLOATS * (int)sizeof(float);

    static bool attr_set = false;
    if (!attr_set) {
        cudaFuncSetAttribute(rbf_kernel,
                             cudaFuncAttributeMaxDynamicSharedMemorySize,
                             smem_bytes);
        attr_set = true;
    }

    const int grid = (nrows + ROWS_TILE - 1) / ROWS_TILE;
    rbf_kernel<<<grid, THREADS, smem_bytes>>>(x, w, out, nrows);
}

// round 2
// speedup vs baseline: 1.4115x; 1.4115x over previous
#include <cuda_runtime.h>

#define K          84
#define CHUNKS     21          // K/4  (float4 chunks per row)
#define NPROTO     10
#define THREADS    128
#define STAGE_ROWS 256         // rows per pipeline stage (2 rows / thread)
#define STAGE_FLOATS (STAGE_ROWS * K)        // 21504
#define STAGE_VEC4   (STAGE_FLOATS / 4)      // 5376
#define COPIES_PER_THREAD (STAGE_VEC4 / THREADS)  // 42

// dynamic smem:
//   buf[2][STAGE_FLOATS]                  2 * 86016 B
//   wblk[CHUNKS*NPROTO] ulonglong2        210 * 16 B = 3360 B
//   w2[16] floats                         64 B
#define SMEM_BYTES (2 * STAGE_FLOATS * 4 + CHUNKS * NPROTO * 16 + 64)

__device__ __forceinline__ void ffma2(unsigned long long &d,
                                      unsigned long long a,
                                      unsigned long long b) {
    asm("fma.rn.f32x2 %0, %1, %2, %0;" : "+l"(d) : "l"(a), "l"(b));
}
__device__ __forceinline__ float f2lo(unsigned long long v) {
    return __int_as_float((unsigned)(v & 0xffffffffULL));
}
__device__ __forceinline__ float f2hi(unsigned long long v) {
    return __int_as_float((unsigned)(v >> 32));
}
__device__ __forceinline__ void cp_async16(unsigned smem_addr, const void* gptr) {
    asm volatile("cp.async.cg.shared.global [%0], [%1], 16;\n"
                 :: "r"(smem_addr), "l"(gptr));
}
__device__ __forceinline__ void cp_commit() {
    asm volatile("cp.async.commit_group;\n" ::: "memory");
}
__device__ __forceinline__ void cp_wait1() {
    asm volatile("cp.async.wait_group 1;\n" ::: "memory");
}

__global__ void __launch_bounds__(THREADS, 1)
rbf_kernel(const float* __restrict__ x,
           const float* __restrict__ weight,
           float* __restrict__ out,
           int nrows) {
    extern __shared__ __align__(16) float smem[];
    float* s_buf0 = smem;                                 // [STAGE_FLOATS]
    float* s_buf1 = smem + STAGE_FLOATS;                  // [STAGE_FLOATS]
    ulonglong2* s_w = (ulonglong2*)(smem + 2 * STAGE_FLOATS); // [CHUNKS*NPROTO]
    float* s_w2 = (float*)(s_w + CHUNKS * NPROTO);        // [16]

    const int t = threadIdx.x;

    // ---- build weight blocks: s_w[c*10+k] = {pair(4c,4c+1), pair(4c+2,4c+3)} of proto k
    for (int i = t; i < CHUNKS * NPROTO; i += THREADS) {
        int c = i / NPROTO;
        int k = i - c * NPROTO;
        const float4 v = *(const float4*)(weight + k * K + 4 * c);
        ulonglong2 u;
        u.x = ((unsigned long long)__float_as_uint(v.y) << 32) | __float_as_uint(v.x);
        u.y = ((unsigned long long)__float_as_uint(v.w) << 32) | __float_as_uint(v.z);
        s_w[i] = u;
    }
    if (t < NPROTO) {
        float s = 0.f;
        #pragma unroll
        for (int j = 0; j < K; j++) { float w = weight[t * K + j]; s += w * w; }
        s_w2[t] = s;
    }

    const int nstages = (nrows + STAGE_ROWS - 1) / STAGE_ROWS;  // 2048 here
    const int step = gridDim.x;
    // stage indices for this CTA: blockIdx.x, +step, +2*step, ...
    int count = 0;
    for (long long s = blockIdx.x; s < nstages; s += step) count++;

    unsigned buf_addr[2];
    buf_addr[0] = (unsigned)__cvta_generic_to_shared(s_buf0);
    buf_addr[1] = (unsigned)__cvta_generic_to_shared(s_buf1);
    float* bufs[2] = { s_buf0, s_buf1 };

    // issue all cp.asyncs for local iteration j into buffer j%2
    auto issue_stage = [&](int j) {
        long long stage = (long long)blockIdx.x + (long long)j * step;
        const float4* gx = (const float4*)x + stage * STAGE_VEC4;
        unsigned dst = buf_addr[j & 1] + t * 16;
        const float4* src = gx + t;
        long long remaining4 = ((long long)nrows * K) / 4 - stage * STAGE_VEC4;
        if (remaining4 >= STAGE_VEC4) {
            #pragma unroll
            for (int i = 0; i < COPIES_PER_THREAD; i++)
                cp_async16(dst + i * THREADS * 16, src + i * THREADS);
        } else {
            #pragma unroll
            for (int i = 0; i < COPIES_PER_THREAD; i++)
                if (i * THREADS + t < remaining4)
                    cp_async16(dst + i * THREADS * 16, src + i * THREADS);
        }
    };

    // ---- pipeline prologue ----
    if (count > 0) issue_stage(0);
    cp_commit();
    if (count > 1) issue_stage(1);
    cp_commit();

    __syncthreads();   // also covers s_w / s_w2 init

    for (int j = 0; j < count; j++) {
        cp_wait1();
        __syncthreads();

        const long long stage = (long long)blockIdx.x + (long long)j * step;
        const float* sx = bufs[j & 1];

        const ulonglong2* rowA = (const ulonglong2*)(sx + t * K);
        const ulonglong2* rowB = (const ulonglong2*)(sx + (t + THREADS) * K);

        unsigned long long accA[NPROTO], accB[NPROTO];
        unsigned long long x2a = 0ULL, x2b = 0ULL;
        #pragma unroll
        for (int k = 0; k < NPROTO; k++) { accA[k] = 0ULL; accB[k] = 0ULL; }

        #pragma unroll
        for (int c = 0; c < CHUNKS; c++) {
            ulonglong2 va = rowA[c];
            ulonglong2 vb = rowB[c];
            ffma2(x2a, va.x, va.x);
            ffma2(x2a, va.y, va.y);
            ffma2(x2b, vb.x, vb.x);
            ffma2(x2b, vb.y, vb.y);
            #pragma unroll
            for (int k = 0; k < NPROTO; k++) {
                ulonglong2 wv = s_w[c * NPROTO + k];
                ffma2(accA[k], va.x, wv.x);
                ffma2(accA[k], va.y, wv.y);
                ffma2(accB[k], vb.x, wv.x);
                ffma2(accB[k], vb.y, wv.y);
            }
        }

        float x2A = f2lo(x2a) + f2hi(x2a);
        float x2B = f2lo(x2b) + f2hi(x2b);

        const long long rA = stage * STAGE_ROWS + t;
        const long long rB = rA + THREADS;

        if (rA < nrows) {
            float2* o = (float2*)(out + rA * NPROTO);
            #pragma unroll
            for (int k = 0; k < 5; k++) {
                float w2a = s_w2[2 * k], w2b = s_w2[2 * k + 1];
                o[k] = make_float2(
                    fmaf(-2.f, f2lo(accA[2 * k])     + f2hi(accA[2 * k]),     x2A + w2a),
                    fmaf(-2.f, f2lo(accA[2 * k + 1]) + f2hi(accA[2 * k + 1]), x2A + w2b));
            }
        }
        if (rB < nrows) {
            float2* o = (float2*)(out + rB * NPROTO);
            #pragma unroll
            for (int k = 0; k < 5; k++) {
                float w2a = s_w2[2 * k], w2b = s_w2[2 * k + 1];
                o[k] = make_float2(
                    fmaf(-2.f, f2lo(accB[2 * k])     + f2hi(accB[2 * k]),     x2B + w2a),
                    fmaf(-2.f, f2lo(accB[2 * k + 1]) + f2hi(accB[2 * k + 1]), x2B + w2b));
            }
        }

        __syncthreads();                 // everyone done reading buffer j%2
        if (j + 2 < count) issue_stage(j + 2);
        cp_commit();
    }
}

extern "C" void kernel_launch(void* const* d_in, const int* in_sizes, int n_in,
                              void* d_out, int out_size) {
    const float* x = (const float*)d_in[0];
    const float* w = (const float*)d_in[1];
    float* out = (float*)d_out;

    const int nrows = in_sizes[0] / K;   // 524288

    static int nsm = 0;
    if (nsm == 0) {
        cudaFuncSetAttribute(rbf_kernel,
                             cudaFuncAttributeMaxDynamicSharedMemorySize,
                             SMEM_BYTES);
        cudaDeviceGetAttribute(&nsm, cudaDevAttrMultiProcessorCount, 0);
        if (nsm <= 0) nsm = 148;
    }

    rbf_kernel<<<nsm, THREADS, SMEM_BYTES>>>(x, w, out, nrows);
}